// round 12
// baseline (speedup 1.0000x reference)
#include <cuda_runtime.h>
#include <cuda_bf16.h>
#include <math.h>
#include <stdint.h>

#define RES   4096
#define DD    128
#define NN    256
#define BB    8
#define SS    256
#define VV    50257
#define LL    2
#define WROWS 50304          // 393 * 128, padded vocab rows
#define NTILES 393
#define MTILES 16
#define UNITS  (NTILES * MTILES)   // 6288
#define CHUNKS 444                 // 148 * 3 -> exactly 3 waves

// Constants matching the reference's fp32 casts of python doubles
#define PHIF   ((float)1.6180339887498948482045868343656381177203)
#define STEPF  ((float)(6.2831853071795864769252867665590 / 4096.0))
#define SCALEF ((float)(4096.0 / 6.2831853071795864769252867665590))

// Scratch (no allocation allowed)
__device__ float g_sin[RES];
__device__ float g_cos[RES];
__device__ float g_X[SS * BB * DD];   // rows m = t*8 + b, 128 cols

// Pre-split bf16 hi/lo planes (row-major: row*128 bf16 = 256B rows)
__device__ __align__(16) __nv_bfloat16 g_Wh[WROWS * DD];
__device__ __align__(16) __nv_bfloat16 g_Wl[WROWS * DD];
__device__ __align__(16) __nv_bfloat16 g_Xh[SS * BB * DD];
__device__ __align__(16) __nv_bfloat16 g_Xl[SS * BB * DD];

// ===========================================================================
// Helpers
// ===========================================================================
__device__ __forceinline__ uint32_t smem_u32(const void* p) {
    uint32_t a;
    asm("{ .reg .u64 t; cvta.to.shared.u64 t, %1; cvt.u32.u64 %0, t; }"
        : "=r"(a) : "l"(p));
    return a;
}

__device__ __forceinline__ uint32_t pk(__nv_bfloat16 a, __nv_bfloat16 b) {
    uint16_t ua = *(uint16_t*)&a, ub = *(uint16_t*)&b;
    return (uint32_t)ua | ((uint32_t)ub << 16);
}

#define LDMATRIX_X4(r0, r1, r2, r3, addr)                                     \
    asm volatile("ldmatrix.sync.aligned.m8n8.x4.shared.b16 {%0,%1,%2,%3}, [%4];" \
        : "=r"(r0), "=r"(r1), "=r"(r2), "=r"(r3) : "r"(addr))

#define MMA_BF16(c, a0, a1, a2, a3, b0, b1)                                   \
    asm volatile("mma.sync.aligned.m16n8k16.row.col.f32.bf16.bf16.f32 "       \
        "{%0,%1,%2,%3}, {%4,%5,%6,%7}, {%8,%9}, {%0,%1,%2,%3};"               \
        : "+f"((c)[0]), "+f"((c)[1]), "+f"((c)[2]), "+f"((c)[3])              \
        : "r"(a0), "r"(a1), "r"(a2), "r"(a3), "r"(b0), "r"(b1))

#define CP_ASYNC16(smaddr, gptr)                                              \
    asm volatile("cp.async.cg.shared.global [%0], [%1], 16;"                  \
        :: "r"(smaddr), "l"(gptr))
#define CP_COMMIT() asm volatile("cp.async.commit_group;" ::: "memory")
#define CP_WAIT0()  asm volatile("cp.async.wait_group 0;" ::: "memory")
#define CP_WAIT1()  asm volatile("cp.async.wait_group 1;" ::: "memory")
#define GBAR(id)    asm volatile("bar.sync %0, 256;" :: "r"(id) : "memory")

// ---------------------------------------------------------------------------
// Kernel 0: build sin/cos tables exactly like the reference
// ---------------------------------------------------------------------------
__global__ void k_tables() {
    int i = blockIdx.x * blockDim.x + threadIdx.x;
    if (i < RES) {
        float a = __fmul_rn((float)i, STEPF);
        g_sin[i] = sinf(a);
        g_cos[i] = cosf(a);
    }
}

// ---------------------------------------------------------------------------
// Kernel 1: elementwise recurrence over t (bit-exact path, unchanged)
// ---------------------------------------------------------------------------
__global__ void k_recur(const int* __restrict__ ids,
                        const float* __restrict__ emb,
                        float* __restrict__ out) {
    __shared__ float s_sin[RES];
    __shared__ float s_cos[RES];
    __shared__ int   s_ids[SS];

    int b = blockIdx.x;
    int d = threadIdx.x;   // 128 threads

    for (int i = d; i < RES; i += 128) { s_sin[i] = g_sin[i]; s_cos[i] = g_cos[i]; }
    for (int i = d; i < SS;  i += 128) s_ids[i] = ids[b * SS + i];
    __syncthreads();

    float hr = 0.0f, hi = 0.0f;

    for (int t0 = 0; t0 < SS; t0 += 8) {
        float wv[8], bv[8];
#pragma unroll
        for (int j = 0; j < 8; ++j) {
            const float* e = emb + (size_t)s_ids[t0 + j] * (2 * DD);
            wv[j] = e[d];
            bv[j] = e[DD + d];
        }
#pragma unroll
        for (int j = 0; j < 8; ++j) {
            int   t     = t0 + j;
            float tphi  = __fmul_rn((float)t, PHIF);
            float num   = __fadd_rn(hr, hi);
            float den   = __fadd_rn(1.0f, fabsf(wv[j]));
            float theta = __fadd_rn(__fadd_rn(__fdiv_rn(num, den), bv[j]), tphi);
            int   idx   = __float2int_rn(__fmul_rn(theta, SCALEF)) & (RES - 1);
            hi = s_sin[idx];
            hr = s_cos[idx];
            g_X[(size_t)t * (BB * DD) + b * DD + d] = __fadd_rn(hr, hi);
        }
    }

    size_t base = (size_t)BB * SS * VV;
    out[base + b * DD + d]            = hr;  // h_real
    out[base + BB * DD + b * DD + d]  = hi;  // h_imag
}

// ---------------------------------------------------------------------------
// fp32 -> bf16 hi/lo split of a float4
// ---------------------------------------------------------------------------
__device__ __forceinline__ void split4(float4 v, uint2& hp, uint2& lp) {
    __nv_bfloat16 h0 = __float2bfloat16(v.x);
    __nv_bfloat16 h1 = __float2bfloat16(v.y);
    __nv_bfloat16 h2 = __float2bfloat16(v.z);
    __nv_bfloat16 h3 = __float2bfloat16(v.w);
    __nv_bfloat16 l0 = __float2bfloat16(v.x - __bfloat162float(h0));
    __nv_bfloat16 l1 = __float2bfloat16(v.y - __bfloat162float(h1));
    __nv_bfloat16 l2 = __float2bfloat16(v.z - __bfloat162float(h2));
    __nv_bfloat16 l3 = __float2bfloat16(v.w - __bfloat162float(h3));
    hp = make_uint2(pk(h0, h1), pk(h2, h3));
    lp = make_uint2(pk(l0, l1), pk(l2, l3));
}

// ---------------------------------------------------------------------------
// Kernel 2: the two MLP layers. Restructured:
//  - Phase B reads Wr/Wi rows directly from global (L2-resident across all
//    256 blocks) -> no smem weight tiles, no per-chunk barriers.
//  - smem = tables 32K + x 4K + cs/sn 16K = 53KB -> 4 CTAs/SM, one wave.
//  - Epilogue writes the bf16 hi/lo planes of X directly (split fused).
// ---------------------------------------------------------------------------
__global__ void __launch_bounds__(256)
k_layers(const float* __restrict__ W,
         const float* __restrict__ bias,
         const float* __restrict__ Wr,
         const float* __restrict__ Wi) {
    extern __shared__ float sm[];
    float* s_sin = sm;                  // 4096
    float* s_cos = s_sin + RES;         // 4096
    float* s_x   = s_cos + RES;         // 1024  (8 x 128)
    float* s_cs  = s_x + BB * DD;       // 2048  (8 x 256)
    float* s_sn  = s_cs + BB * NN;      // 2048

    int tid = threadIdx.x;
    int t   = blockIdx.x;

    for (int i = tid; i < RES; i += 256) { s_sin[i] = g_sin[i]; s_cos[i] = g_cos[i]; }
    float* gx = g_X + (size_t)t * (BB * DD);
    for (int i = tid; i < BB * DD; i += 256) s_x[i] = gx[i];
    __syncthreads();

    float tphi = __fmul_rn((float)t, PHIF);
    int n    = tid;
    int dcol = tid & 127;
    int bhi  = tid >> 7;   // 0 or 1

    for (int layer = 0; layer < LL; ++layer) {
        // ---- Phase A: th = x @ W^T + b + tphi -> table lookups into s_cs/s_sn
        const float4* Wn = (const float4*)(W + ((size_t)layer * NN + n) * DD);
        const float4* x4 = (const float4*)s_x;
        float acc[8];
#pragma unroll
        for (int bb = 0; bb < 8; ++bb) acc[bb] = 0.0f;
#pragma unroll 8
        for (int q = 0; q < 32; ++q) {
            float4 w = Wn[q];
#pragma unroll
            for (int bb = 0; bb < 8; ++bb) {
                float4 xv = x4[bb * 32 + q];
                acc[bb] += w.x * xv.x + w.y * xv.y + w.z * xv.z + w.w * xv.w;
            }
        }
        float bsn = bias[layer * NN + n];
#pragma unroll
        for (int bb = 0; bb < 8; ++bb) {
            float th  = acc[bb] + bsn + tphi;
            int   idx = __float2int_rn(__fmul_rn(th, SCALEF)) & (RES - 1);
            s_sn[bb * NN + n] = s_sin[idx];
            s_cs[bb * NN + n] = s_cos[idx];
        }
        __syncthreads();

        // ---- Phase B: o[b][d] = cs @ Wr^T + sn @ Wi^T, Wr/Wi via L2 ----
        float o[4] = {0.0f, 0.0f, 0.0f, 0.0f};
        const float4* wr4 = (const float4*)(Wr + ((size_t)layer * DD + dcol) * NN);
        const float4* wi4 = (const float4*)(Wi + ((size_t)layer * DD + dcol) * NN);
#pragma unroll 8
        for (int q = 0; q < 64; ++q) {          // n = 4q .. 4q+3, ascending
            float4 wr = wr4[q];
            float4 wi = wi4[q];
#pragma unroll
            for (int p = 0; p < 4; ++p) {
                int bb = bhi + 2 * p;
                float4 cs = ((const float4*)(s_cs + bb * NN))[q];
                float4 sn = ((const float4*)(s_sn + bb * NN))[q];
                o[p] += cs.x * wr.x + cs.y * wr.y + cs.z * wr.z + cs.w * wr.w
                      + sn.x * wi.x + sn.y * wi.y + sn.z * wi.z + sn.w * wi.w;
            }
        }
        __syncthreads();   // everyone done reading s_cs/s_sn (layer) & s_x unread now
#pragma unroll
        for (int p = 0; p < 4; ++p) {
            int bb = bhi + 2 * p;
            float ov = o[p];
            float sv = ov / (1.0f + expf(-ov));   // o * sigmoid(o)
            s_x[bb * DD + dcol] += sv;
        }
        __syncthreads();
    }

    // ---- epilogue: write bf16 hi/lo planes of final x (split fused) ----
    {
        const float4* sx4 = (const float4*)s_x;
        float4 v = sx4[tid];                       // 256 float4 = 1024 floats
        uint2 hp, lp;
        split4(v, hp, lp);
        ((uint2*)g_Xh)[(size_t)t * 256 + tid] = hp;
        ((uint2*)g_Xl)[(size_t)t * 256 + tid] = lp;
    }
}

// ---------------------------------------------------------------------------
// Split kernel for out_w: fp32 -> bf16 hi/lo planes (row-major)
// ---------------------------------------------------------------------------
__global__ void k_split_w(const float* __restrict__ Wv) {
    int f = blockIdx.x * blockDim.x + threadIdx.x;   // 0 .. WROWS*32-1
    int r = f >> 5, kq = f & 31;
    float4 v = make_float4(0.f, 0.f, 0.f, 0.f);
    if (r < VV) v = ((const float4*)Wv)[(size_t)r * 32 + kq];
    uint2 hp, lp;
    split4(v, hp, lp);
    ((uint2*)g_Wh)[f] = hp;
    ((uint2*)g_Wl)[f] = lp;
}

// ---------------------------------------------------------------------------
// Kernel 3: work-list logits GEMM with TWO independent 8-warp groups.
//   444 CTAs (3 waves) x 512 thr. Unit = (nt, mt): 128x128 output tile.
//   Group g handles rows [g*64, g*64+64) of every tile with its OWN
//   double-buffered 32KB A planes and named-barrier sync -> group0's
//   epilogue overlaps group1's MMAs. B (64KB) is CTA-shared, reloaded only
//   at nt boundaries (full __syncthreads, uniform condition).
// smem: BH 32K | BL 32K | G0A0 32K | G0A1 32K | G1A0 32K | G1A1 32K = 192K
// ---------------------------------------------------------------------------
#define PB_BH 0u
#define PB_BL 32768u
#define PB_A  65536u
#define SMEM_PIPE 196608u

__device__ __forceinline__ void issue_B(uint32_t sb, int nt, int tid) {
    const char* gWh = (const char*)g_Wh;
    const char* gWl = (const char*)g_Wl;
#pragma unroll
    for (int i = 0; i < 4; ++i) {
        int f = tid + 512 * i;            // 0..2047
        int r = f >> 4, u = f & 15;
        uint32_t so = (uint32_t)(r * 256 + ((u ^ (r & 7)) << 4));
        size_t   go = (size_t)(nt * 128 + r) * 256 + u * 16;
        CP_ASYNC16(sb + PB_BH + so, gWh + go);
        CP_ASYNC16(sb + PB_BL + so, gWl + go);
    }
}

// Load 64 rows (this group's half of an M-tile) into a 32KB buffer.
__device__ __forceinline__ void issue_Ag(uint32_t abuf, int mt, int grp, int gtid) {
    const char* gXh = (const char*)g_Xh;
    const char* gXl = (const char*)g_Xl;
#pragma unroll
    for (int i = 0; i < 4; ++i) {
        int f = gtid + 256 * i;           // 0..1023
        int r = f >> 4, u = f & 15;       // r: 0..63
        uint32_t so = (uint32_t)(r * 256 + ((u ^ (r & 7)) << 4));
        size_t   go = (size_t)(mt * 128 + grp * 64 + r) * 256 + u * 16;
        CP_ASYNC16(abuf + so, gXh + go);
        CP_ASYNC16(abuf + 16384u + so, gXl + go);
    }
}

__global__ void __launch_bounds__(512, 1)
k_logits_wg(float* __restrict__ out) {
    extern __shared__ char smc[];
    uint32_t sb = smem_u32(smc);

    int tid  = threadIdx.x;
    int lane = tid & 31;
    int wid  = tid >> 5;
    int grp  = wid >> 3;           // 0 or 1
    int gwid = wid & 7;            // warp within group
    int gtid = tid & 255;
    int bar  = 1 + grp;
    int cid  = blockIdx.x;

    int start = (cid * UNITS) / CHUNKS;
    int end   = ((cid + 1) * UNITS) / CHUNKS;

    int wm = gwid & 1;             // M offset within 64-row half: 0/32
    int wn = gwid >> 1;            // N offset: 0/32/64/96
    int g  = lane >> 3;
    int l7 = lane & 7;
    int ra = l7 + (g & 1) * 8;
    int ua = g >> 1;
    int rb = l7 + (g >> 1) * 8;
    int ub = g & 1;

    // A buffer bases for this group (hi plane; lo at +16384)
    uint32_t abuf0 = sb + PB_A + (uint32_t)grp * 65536u;
    uint32_t abuf1 = abuf0 + 32768u;

    uint32_t arel[2];
#pragma unroll
    for (int mf = 0; mf < 2; ++mf)
        arel[mf] = (uint32_t)((wm * 32 + mf * 16 + ra) * 256);
    uint32_t brow[2];
#pragma unroll
    for (int nf2 = 0; nf2 < 2; ++nf2)
        brow[nf2] = sb + PB_BH + (uint32_t)((wn * 32 + nf2 * 16 + rb) * 256);

    int u = start;
    int cur_nt = u >> 4;
    issue_B(sb, cur_nt, tid);
    issue_Ag(abuf0, u & 15, grp, gtid);
    CP_COMMIT();
    int parity = 0;
    bool freshB = true;

    while (u < end) {
        int nxt = u + 1;
        bool havenext = (nxt < end);
        bool samen = havenext && ((nxt >> 4) == cur_nt);
        if (samen) {
            issue_Ag(parity ? abuf0 : abuf1, nxt & 15, grp, gtid);
            CP_COMMIT();
            CP_WAIT1();
        } else {
            CP_WAIT0();
        }
        if (freshB) { __syncthreads(); freshB = false; }
        else        { GBAR(bar); }

        uint32_t abase = parity ? abuf1 : abuf0;

        float acc[2][4][4];
#pragma unroll
        for (int i = 0; i < 2; ++i)
#pragma unroll
            for (int j = 0; j < 4; ++j)
#pragma unroll
                for (int q = 0; q < 4; ++q) acc[i][j][q] = 0.0f;

#pragma unroll
        for (int k16 = 0; k16 < 8; ++k16) {
            uint32_t uxa = (uint32_t)(((2 * k16 + ua) ^ l7) << 4);
            uint32_t uxb = (uint32_t)(((2 * k16 + ub) ^ l7) << 4);

            uint32_t aH[2][4], bH[2][4];
#pragma unroll
            for (int mf = 0; mf < 2; ++mf)
                LDMATRIX_X4(aH[mf][0], aH[mf][1], aH[mf][2], aH[mf][3],
                            abase + arel[mf] + uxa);
#pragma unroll
            for (int nf2 = 0; nf2 < 2; ++nf2)
                LDMATRIX_X4(bH[nf2][0], bH[nf2][1], bH[nf2][2], bH[nf2][3],
                            brow[nf2] + uxb);

            // Term 1: Ah * Bh
#pragma unroll
            for (int mf = 0; mf < 2; ++mf)
#pragma unroll
                for (int nf = 0; nf < 4; ++nf)
                    MMA_BF16(acc[mf][nf], aH[mf][0], aH[mf][1], aH[mf][2], aH[mf][3],
                             bH[nf >> 1][(nf & 1) * 2], bH[nf >> 1][(nf & 1) * 2 + 1]);

            // Term 2: Ah * Bl
            {
                uint32_t bL[2][4];
#pragma unroll
                for (int nf2 = 0; nf2 < 2; ++nf2)
                    LDMATRIX_X4(bL[nf2][0], bL[nf2][1], bL[nf2][2], bL[nf2][3],
                                brow[nf2] + 32768u + uxb);
#pragma unroll
                for (int mf = 0; mf < 2; ++mf)
#pragma unroll
                    for (int nf = 0; nf < 4; ++nf)
                        MMA_BF16(acc[mf][nf], aH[mf][0], aH[mf][1], aH[mf][2], aH[mf][3],
                                 bL[nf >> 1][(nf & 1) * 2], bL[nf >> 1][(nf & 1) * 2 + 1]);
            }

            // Term 3: Al * Bh
            {
                uint32_t aL[2][4];
#pragma unroll
                for (int mf = 0; mf < 2; ++mf)
                    LDMATRIX_X4(aL[mf][0], aL[mf][1], aL[mf][2], aL[mf][3],
                                abase + 16384u + arel[mf] + uxa);
#pragma unroll
                for (int mf = 0; mf < 2; ++mf)
#pragma unroll
                    for (int nf = 0; nf < 4; ++nf)
                        MMA_BF16(acc[mf][nf], aL[mf][0], aL[mf][1], aL[mf][2], aL[mf][3],
                                 bH[nf >> 1][(nf & 1) * 2], bH[nf >> 1][(nf & 1) * 2 + 1]);
            }
        }

        // ---- epilogue: write into (B,S,V) layout ----
        {
            int mt = u & 15;
            bool fullT = (cur_nt != NTILES - 1);
            int m0 = mt * 128 + grp * 64;
            int cbase = cur_nt * 128 + wn * 32 + (lane & 3) * 2;
#pragma unroll
            for (int mf = 0; mf < 2; ++mf) {
                int rr = m0 + wm * 32 + mf * 16 + (lane >> 2);
#pragma unroll
                for (int half = 0; half < 2; ++half) {
                    int m = rr + half * 8;
                    float* orow = out + (size_t)(m & 7) * SS * VV + (size_t)(m >> 3) * VV;
#pragma unroll
                    for (int nf = 0; nf < 4; ++nf) {
                        int c = cbase + nf * 8;
                        float v0 = acc[mf][nf][half * 2 + 0];
                        float v1 = acc[mf][nf][half * 2 + 1];
                        if (fullT) {
                            orow[c]     = v0;
                            orow[c + 1] = v1;
                        } else {
                            if (c < VV)     orow[c]     = v0;
                            if (c + 1 < VV) orow[c + 1] = v1;
                        }
                    }
                }
            }
        }

        if (havenext && !samen) {
            // nt boundary: all warps (both groups) must be done with B
            __syncthreads();
            cur_nt = nxt >> 4;
            issue_B(sb, cur_nt, tid);
            issue_Ag(parity ? abuf0 : abuf1, nxt & 15, grp, gtid);
            CP_COMMIT();
            freshB = true;
        } else {
            GBAR(bar);   // group's A buffer safe to refill next iteration
        }
        parity ^= 1;
        u = nxt;
    }
}

// ---------------------------------------------------------------------------
extern "C" void kernel_launch(void* const* d_in, const int* in_sizes, int n_in,
                              void* d_out, int out_size) {
    const int*   input_ids = (const int*)  d_in[0];
    const float* emb       = (const float*)d_in[1];
    const float* layer_W   = (const float*)d_in[2];
    const float* layer_b   = (const float*)d_in[3];
    const float* layer_Wr  = (const float*)d_in[4];
    const float* layer_Wi  = (const float*)d_in[5];
    const float* out_w     = (const float*)d_in[6];
    float* out = (float*)d_out;

    const int smem_layers = (2 * RES + BB * DD + 2 * BB * NN) * sizeof(float);
    cudaFuncSetAttribute(k_layers,    cudaFuncAttributeMaxDynamicSharedMemorySize, smem_layers);
    cudaFuncSetAttribute(k_logits_wg, cudaFuncAttributeMaxDynamicSharedMemorySize, (int)SMEM_PIPE);

    k_tables<<<(RES + 255) / 256, 256>>>();
    k_recur<<<BB, DD>>>(input_ids, emb, out);
    k_split_w<<<(WROWS * 32) / 256, 256>>>(out_w);   // independent of recur/layers
    k_layers<<<SS, 256, smem_layers>>>(layer_W, layer_b, layer_Wr, layer_Wi);

    k_logits_wg<<<CHUNKS, 512, SMEM_PIPE>>>(out);
}

// round 13
// speedup vs baseline: 1.0374x; 1.0374x over previous
#include <cuda_runtime.h>
#include <cuda_bf16.h>
#include <math.h>
#include <stdint.h>

#define RES   4096
#define DD    128
#define NN    256
#define BB    8
#define SS    256
#define VV    50257
#define LL    2
#define WROWS 50304          // 393 * 128, padded vocab rows
#define NTILES 393
#define MTILES 16
#define UNITS  (NTILES * MTILES)   // 6288
#define CHUNKS 444                 // 148 * 3 -> exactly 3 waves

// Constants matching the reference's fp32 casts of python doubles
#define PHIF   ((float)1.6180339887498948482045868343656381177203)
#define STEPF  ((float)(6.2831853071795864769252867665590 / 4096.0))
#define SCALEF ((float)(4096.0 / 6.2831853071795864769252867665590))

// Scratch (no allocation allowed)
__device__ float g_sin[RES];
__device__ float g_cos[RES];
__device__ float g_X[SS * BB * DD];   // rows m = t*8 + b, 128 cols

// Pre-split bf16 hi/lo planes (row-major: row*128 bf16 = 256B rows)
__device__ __align__(16) __nv_bfloat16 g_Wh[WROWS * DD];
__device__ __align__(16) __nv_bfloat16 g_Wl[WROWS * DD];
__device__ __align__(16) __nv_bfloat16 g_Xh[SS * BB * DD];
__device__ __align__(16) __nv_bfloat16 g_Xl[SS * BB * DD];

// ===========================================================================
// Helpers
// ===========================================================================
__device__ __forceinline__ uint32_t smem_u32(const void* p) {
    uint32_t a;
    asm("{ .reg .u64 t; cvta.to.shared.u64 t, %1; cvt.u32.u64 %0, t; }"
        : "=r"(a) : "l"(p));
    return a;
}

__device__ __forceinline__ uint32_t pk(__nv_bfloat16 a, __nv_bfloat16 b) {
    uint16_t ua = *(uint16_t*)&a, ub = *(uint16_t*)&b;
    return (uint32_t)ua | ((uint32_t)ub << 16);
}

#define LDMATRIX_X4(r0, r1, r2, r3, addr)                                     \
    asm volatile("ldmatrix.sync.aligned.m8n8.x4.shared.b16 {%0,%1,%2,%3}, [%4];" \
        : "=r"(r0), "=r"(r1), "=r"(r2), "=r"(r3) : "r"(addr))

#define MMA_BF16(c, a0, a1, a2, a3, b0, b1)                                   \
    asm volatile("mma.sync.aligned.m16n8k16.row.col.f32.bf16.bf16.f32 "       \
        "{%0,%1,%2,%3}, {%4,%5,%6,%7}, {%8,%9}, {%0,%1,%2,%3};"               \
        : "+f"((c)[0]), "+f"((c)[1]), "+f"((c)[2]), "+f"((c)[3])              \
        : "r"(a0), "r"(a1), "r"(a2), "r"(a3), "r"(b0), "r"(b1))

#define CP_ASYNC16(smaddr, gptr)                                              \
    asm volatile("cp.async.cg.shared.global [%0], [%1], 16;"                  \
        :: "r"(smaddr), "l"(gptr))
#define CP_COMMIT() asm volatile("cp.async.commit_group;" ::: "memory")
#define CP_WAIT0()  asm volatile("cp.async.wait_group 0;" ::: "memory")
#define CP_WAIT1()  asm volatile("cp.async.wait_group 1;" ::: "memory")
#define GBAR(id)    asm volatile("bar.sync %0, 256;" :: "r"(id) : "memory")

// ---------------------------------------------------------------------------
// Kernel 0: build sin/cos tables exactly like the reference
// ---------------------------------------------------------------------------
__global__ void k_tables() {
    int i = blockIdx.x * blockDim.x + threadIdx.x;
    if (i < RES) {
        float a = __fmul_rn((float)i, STEPF);
        g_sin[i] = sinf(a);
        g_cos[i] = cosf(a);
    }
}

// ---------------------------------------------------------------------------
// Kernel 1: elementwise recurrence over t (bit-exact path, unchanged)
// ---------------------------------------------------------------------------
__global__ void k_recur(const int* __restrict__ ids,
                        const float* __restrict__ emb,
                        float* __restrict__ out) {
    __shared__ float s_sin[RES];
    __shared__ float s_cos[RES];
    __shared__ int   s_ids[SS];

    int b = blockIdx.x;
    int d = threadIdx.x;   // 128 threads

    for (int i = d; i < RES; i += 128) { s_sin[i] = g_sin[i]; s_cos[i] = g_cos[i]; }
    for (int i = d; i < SS;  i += 128) s_ids[i] = ids[b * SS + i];
    __syncthreads();

    float hr = 0.0f, hi = 0.0f;

    for (int t0 = 0; t0 < SS; t0 += 8) {
        float wv[8], bv[8];
#pragma unroll
        for (int j = 0; j < 8; ++j) {
            const float* e = emb + (size_t)s_ids[t0 + j] * (2 * DD);
            wv[j] = e[d];
            bv[j] = e[DD + d];
        }
#pragma unroll
        for (int j = 0; j < 8; ++j) {
            int   t     = t0 + j;
            float tphi  = __fmul_rn((float)t, PHIF);
            float num   = __fadd_rn(hr, hi);
            float den   = __fadd_rn(1.0f, fabsf(wv[j]));
            float theta = __fadd_rn(__fadd_rn(__fdiv_rn(num, den), bv[j]), tphi);
            int   idx   = __float2int_rn(__fmul_rn(theta, SCALEF)) & (RES - 1);
            hi = s_sin[idx];
            hr = s_cos[idx];
            g_X[(size_t)t * (BB * DD) + b * DD + d] = __fadd_rn(hr, hi);
        }
    }

    size_t base = (size_t)BB * SS * VV;
    out[base + b * DD + d]            = hr;  // h_real
    out[base + BB * DD + b * DD + d]  = hi;  // h_imag
}

// ---------------------------------------------------------------------------
// fp32 -> bf16 hi/lo split of a float4
// ---------------------------------------------------------------------------
__device__ __forceinline__ void split4(float4 v, uint2& hp, uint2& lp) {
    __nv_bfloat16 h0 = __float2bfloat16(v.x);
    __nv_bfloat16 h1 = __float2bfloat16(v.y);
    __nv_bfloat16 h2 = __float2bfloat16(v.z);
    __nv_bfloat16 h3 = __float2bfloat16(v.w);
    __nv_bfloat16 l0 = __float2bfloat16(v.x - __bfloat162float(h0));
    __nv_bfloat16 l1 = __float2bfloat16(v.y - __bfloat162float(h1));
    __nv_bfloat16 l2 = __float2bfloat16(v.z - __bfloat162float(h2));
    __nv_bfloat16 l3 = __float2bfloat16(v.w - __bfloat162float(h3));
    hp = make_uint2(pk(h0, h1), pk(h2, h3));
    lp = make_uint2(pk(l0, l1), pk(l2, l3));
}

// ---------------------------------------------------------------------------
// Kernel 2: the two MLP layers, b-split for parallelism.
//   Grid = 512 (2 blocks per timestep; each handles 4 batch rows).
//   Tables read from global (L2-resident, 8 indep lookups/thread/layer),
//   Wr/Wi chunks staged in smem (coalesced), X hi/lo split fused in epilogue.
//   smem ~46KB -> 4 CTAs/SM -> all 512 blocks co-resident in one wave.
// ---------------------------------------------------------------------------
#define NB 4    // batch rows per block
__global__ void __launch_bounds__(256)
k_layers2(const float* __restrict__ W,
          const float* __restrict__ bias,
          const float* __restrict__ Wr,
          const float* __restrict__ Wi) {
    extern __shared__ float sm[];
    float* s_x  = sm;                   // 4 x 128 = 512
    float* s_cs = s_x + NB * DD;        // 4 x 256 = 1024
    float* s_sn = s_cs + NB * NN;       // 1024
    float* s_wr = s_sn + NB * NN;       // 128*36 = 4608
    float* s_wi = s_wr + DD * 36;       // 4608   -> total 11776 fl = 47104 B

    int tid  = threadIdx.x;
    int t    = blockIdx.x >> 1;
    int b0   = (blockIdx.x & 1) * NB;

    float* gx = g_X + (size_t)t * (BB * DD) + b0 * DD;   // 4 rows = 512 floats
    for (int i = tid; i < NB * DD; i += 256) s_x[i] = gx[i];
    __syncthreads();

    float tphi = __fmul_rn((float)t, PHIF);
    int n    = tid;
    int dcol = tid & 127;
    int bhi  = tid >> 7;   // 0 or 1 -> handles local b = bhi, bhi+2 in Phase B

    for (int layer = 0; layer < LL; ++layer) {
        // ---- Phase A: th = x @ W^T + b + tphi -> lookups (global tables)
        const float4* Wn = (const float4*)(W + ((size_t)layer * NN + n) * DD);
        const float4* x4 = (const float4*)s_x;
        float acc[NB];
#pragma unroll
        for (int j = 0; j < NB; ++j) acc[j] = 0.0f;
#pragma unroll 8
        for (int q = 0; q < 32; ++q) {
            float4 w = Wn[q];
#pragma unroll
            for (int j = 0; j < NB; ++j) {
                float4 xv = x4[j * 32 + q];
                acc[j] += w.x * xv.x + w.y * xv.y + w.z * xv.z + w.w * xv.w;
            }
        }
        float bsn = bias[layer * NN + n];
#pragma unroll
        for (int j = 0; j < NB; ++j) {
            float th  = acc[j] + bsn + tphi;
            int   idx = __float2int_rn(__fmul_rn(th, SCALEF)) & (RES - 1);
            s_sn[j * NN + n] = g_sin[idx];
            s_cs[j * NN + n] = g_cos[idx];
        }
        __syncthreads();

        // ---- Phase B: o[b][d] = cs @ Wr^T + sn @ Wi^T (smem weight tiles)
        float o[2] = {0.0f, 0.0f};
        const float* WrL = Wr + (size_t)layer * DD * NN;
        const float* WiL = Wi + (size_t)layer * DD * NN;
        for (int n0 = 0; n0 < NN; n0 += 32) {
#pragma unroll
            for (int l2 = 0; l2 < 16; ++l2) {
                int f  = tid + 256 * l2;   // 0..4095
                int dd = f >> 5, nn2 = f & 31;
                s_wr[dd * 36 + nn2] = WrL[dd * NN + n0 + nn2];
                s_wi[dd * 36 + nn2] = WiL[dd * NN + n0 + nn2];
            }
            __syncthreads();
            const float4* wr4 = (const float4*)(s_wr + dcol * 36);
            const float4* wi4 = (const float4*)(s_wi + dcol * 36);
#pragma unroll
            for (int q = 0; q < 8; ++q) {
                float4 wr = wr4[q];
                float4 wi = wi4[q];
#pragma unroll
                for (int p = 0; p < 2; ++p) {
                    int bb = bhi + 2 * p;
                    float4 cs = ((const float4*)(s_cs + bb * NN + n0))[q];
                    float4 sn = ((const float4*)(s_sn + bb * NN + n0))[q];
                    o[p] += cs.x * wr.x + cs.y * wr.y + cs.z * wr.z + cs.w * wr.w
                          + sn.x * wi.x + sn.y * wi.y + sn.z * wi.z + sn.w * wi.w;
                }
            }
            __syncthreads();
        }
#pragma unroll
        for (int p = 0; p < 2; ++p) {
            int bb = bhi + 2 * p;
            float ov = o[p];
            float sv = ov / (1.0f + expf(-ov));   // o * sigmoid(o)
            s_x[bb * DD + dcol] += sv;
        }
        __syncthreads();
    }

    // ---- epilogue: write bf16 hi/lo planes of final x (split fused) ----
    if (tid < NB * DD / 4) {                      // 128 float4
        float4 v = ((const float4*)s_x)[tid];
        uint2 hp, lp;
        split4(v, hp, lp);
        int r = tid >> 5, u = tid & 31;
        size_t gi = (size_t)(t * BB + b0 + r) * 32 + u;
        ((uint2*)g_Xh)[gi] = hp;
        ((uint2*)g_Xl)[gi] = lp;
    }
}

// ---------------------------------------------------------------------------
// Split kernel for out_w: fp32 -> bf16 hi/lo planes (row-major)
// ---------------------------------------------------------------------------
__global__ void k_split_w(const float* __restrict__ Wv) {
    int f = blockIdx.x * blockDim.x + threadIdx.x;   // 0 .. WROWS*32-1
    int r = f >> 5, kq = f & 31;
    float4 v = make_float4(0.f, 0.f, 0.f, 0.f);
    if (r < VV) v = ((const float4*)Wv)[(size_t)r * 32 + kq];
    uint2 hp, lp;
    split4(v, hp, lp);
    ((uint2*)g_Wh)[f] = hp;
    ((uint2*)g_Wl)[f] = lp;
}

// ---------------------------------------------------------------------------
// Kernel 3: work-list logits GEMM with TWO independent 8-warp groups.
//   (byte-identical to the 409.6us-passing version — do not touch)
// ---------------------------------------------------------------------------
#define PB_BH 0u
#define PB_BL 32768u
#define PB_A  65536u
#define SMEM_PIPE 196608u

__device__ __forceinline__ void issue_B(uint32_t sb, int nt, int tid) {
    const char* gWh = (const char*)g_Wh;
    const char* gWl = (const char*)g_Wl;
#pragma unroll
    for (int i = 0; i < 4; ++i) {
        int f = tid + 512 * i;            // 0..2047
        int r = f >> 4, u = f & 15;
        uint32_t so = (uint32_t)(r * 256 + ((u ^ (r & 7)) << 4));
        size_t   go = (size_t)(nt * 128 + r) * 256 + u * 16;
        CP_ASYNC16(sb + PB_BH + so, gWh + go);
        CP_ASYNC16(sb + PB_BL + so, gWl + go);
    }
}

// Load 64 rows (this group's half of an M-tile) into a 32KB buffer.
__device__ __forceinline__ void issue_Ag(uint32_t abuf, int mt, int grp, int gtid) {
    const char* gXh = (const char*)g_Xh;
    const char* gXl = (const char*)g_Xl;
#pragma unroll
    for (int i = 0; i < 4; ++i) {
        int f = gtid + 256 * i;           // 0..1023
        int r = f >> 4, u = f & 15;       // r: 0..63
        uint32_t so = (uint32_t)(r * 256 + ((u ^ (r & 7)) << 4));
        size_t   go = (size_t)(mt * 128 + grp * 64 + r) * 256 + u * 16;
        CP_ASYNC16(abuf + so, gXh + go);
        CP_ASYNC16(abuf + 16384u + so, gXl + go);
    }
}

__global__ void __launch_bounds__(512, 1)
k_logits_wg(float* __restrict__ out) {
    extern __shared__ char smc[];
    uint32_t sb = smem_u32(smc);

    int tid  = threadIdx.x;
    int lane = tid & 31;
    int wid  = tid >> 5;
    int grp  = wid >> 3;           // 0 or 1
    int gwid = wid & 7;            // warp within group
    int gtid = tid & 255;
    int bar  = 1 + grp;
    int cid  = blockIdx.x;

    int start = (cid * UNITS) / CHUNKS;
    int end   = ((cid + 1) * UNITS) / CHUNKS;

    int wm = gwid & 1;             // M offset within 64-row half: 0/32
    int wn = gwid >> 1;            // N offset: 0/32/64/96
    int g  = lane >> 3;
    int l7 = lane & 7;
    int ra = l7 + (g & 1) * 8;
    int ua = g >> 1;
    int rb = l7 + (g >> 1) * 8;
    int ub = g & 1;

    // A buffer bases for this group (hi plane; lo at +16384)
    uint32_t abuf0 = sb + PB_A + (uint32_t)grp * 65536u;
    uint32_t abuf1 = abuf0 + 32768u;

    uint32_t arel[2];
#pragma unroll
    for (int mf = 0; mf < 2; ++mf)
        arel[mf] = (uint32_t)((wm * 32 + mf * 16 + ra) * 256);
    uint32_t brow[2];
#pragma unroll
    for (int nf2 = 0; nf2 < 2; ++nf2)
        brow[nf2] = sb + PB_BH + (uint32_t)((wn * 32 + nf2 * 16 + rb) * 256);

    int u = start;
    int cur_nt = u >> 4;
    issue_B(sb, cur_nt, tid);
    issue_Ag(abuf0, u & 15, grp, gtid);
    CP_COMMIT();
    int parity = 0;
    bool freshB = true;

    while (u < end) {
        int nxt = u + 1;
        bool havenext = (nxt < end);
        bool samen = havenext && ((nxt >> 4) == cur_nt);
        if (samen) {
            issue_Ag(parity ? abuf0 : abuf1, nxt & 15, grp, gtid);
            CP_COMMIT();
            CP_WAIT1();
        } else {
            CP_WAIT0();
        }
        if (freshB) { __syncthreads(); freshB = false; }
        else        { GBAR(bar); }

        uint32_t abase = parity ? abuf1 : abuf0;

        float acc[2][4][4];
#pragma unroll
        for (int i = 0; i < 2; ++i)
#pragma unroll
            for (int j = 0; j < 4; ++j)
#pragma unroll
                for (int q = 0; q < 4; ++q) acc[i][j][q] = 0.0f;

#pragma unroll
        for (int k16 = 0; k16 < 8; ++k16) {
            uint32_t uxa = (uint32_t)(((2 * k16 + ua) ^ l7) << 4);
            uint32_t uxb = (uint32_t)(((2 * k16 + ub) ^ l7) << 4);

            uint32_t aH[2][4], bH[2][4];
#pragma unroll
            for (int mf = 0; mf < 2; ++mf)
                LDMATRIX_X4(aH[mf][0], aH[mf][1], aH[mf][2], aH[mf][3],
                            abase + arel[mf] + uxa);
#pragma unroll
            for (int nf2 = 0; nf2 < 2; ++nf2)
                LDMATRIX_X4(bH[nf2][0], bH[nf2][1], bH[nf2][2], bH[nf2][3],
                            brow[nf2] + uxb);

            // Term 1: Ah * Bh
#pragma unroll
            for (int mf = 0; mf < 2; ++mf)
#pragma unroll
                for (int nf = 0; nf < 4; ++nf)
                    MMA_BF16(acc[mf][nf], aH[mf][0], aH[mf][1], aH[mf][2], aH[mf][3],
                             bH[nf >> 1][(nf & 1) * 2], bH[nf >> 1][(nf & 1) * 2 + 1]);

            // Term 2: Ah * Bl
            {
                uint32_t bL[2][4];
#pragma unroll
                for (int nf2 = 0; nf2 < 2; ++nf2)
                    LDMATRIX_X4(bL[nf2][0], bL[nf2][1], bL[nf2][2], bL[nf2][3],
                                brow[nf2] + 32768u + uxb);
#pragma unroll
                for (int mf = 0; mf < 2; ++mf)
#pragma unroll
                    for (int nf = 0; nf < 4; ++nf)
                        MMA_BF16(acc[mf][nf], aH[mf][0], aH[mf][1], aH[mf][2], aH[mf][3],
                                 bL[nf >> 1][(nf & 1) * 2], bL[nf >> 1][(nf & 1) * 2 + 1]);
            }

            // Term 3: Al * Bh
            {
                uint32_t aL[2][4];
#pragma unroll
                for (int mf = 0; mf < 2; ++mf)
                    LDMATRIX_X4(aL[mf][0], aL[mf][1], aL[mf][2], aL[mf][3],
                                abase + 16384u + arel[mf] + uxa);
#pragma unroll
                for (int mf = 0; mf < 2; ++mf)
#pragma unroll
                    for (int nf = 0; nf < 4; ++nf)
                        MMA_BF16(acc[mf][nf], aL[mf][0], aL[mf][1], aL[mf][2], aL[mf][3],
                                 bH[nf >> 1][(nf & 1) * 2], bH[nf >> 1][(nf & 1) * 2 + 1]);
            }
        }

        // ---- epilogue: write into (B,S,V) layout ----
        {
            int mt = u & 15;
            bool fullT = (cur_nt != NTILES - 1);
            int m0 = mt * 128 + grp * 64;
            int cbase = cur_nt * 128 + wn * 32 + (lane & 3) * 2;
#pragma unroll
            for (int mf = 0; mf < 2; ++mf) {
                int rr = m0 + wm * 32 + mf * 16 + (lane >> 2);
#pragma unroll
                for (int half = 0; half < 2; ++half) {
                    int m = rr + half * 8;
                    float* orow = out + (size_t)(m & 7) * SS * VV + (size_t)(m >> 3) * VV;
#pragma unroll
                    for (int nf = 0; nf < 4; ++nf) {
                        int c = cbase + nf * 8;
                        float v0 = acc[mf][nf][half * 2 + 0];
                        float v1 = acc[mf][nf][half * 2 + 1];
                        if (fullT) {
                            orow[c]     = v0;
                            orow[c + 1] = v1;
                        } else {
                            if (c < VV)     orow[c]     = v0;
                            if (c + 1 < VV) orow[c + 1] = v1;
                        }
                    }
                }
            }
        }

        if (havenext && !samen) {
            // nt boundary: all warps (both groups) must be done with B
            __syncthreads();
            cur_nt = nxt >> 4;
            issue_B(sb, cur_nt, tid);
            issue_Ag(parity ? abuf0 : abuf1, nxt & 15, grp, gtid);
            CP_COMMIT();
            freshB = true;
        } else {
            GBAR(bar);   // group's A buffer safe to refill next iteration
        }
        parity ^= 1;
        u = nxt;
    }
}

// ---------------------------------------------------------------------------
extern "C" void kernel_launch(void* const* d_in, const int* in_sizes, int n_in,
                              void* d_out, int out_size) {
    const int*   input_ids = (const int*)  d_in[0];
    const float* emb       = (const float*)d_in[1];
    const float* layer_W   = (const float*)d_in[2];
    const float* layer_b   = (const float*)d_in[3];
    const float* layer_Wr  = (const float*)d_in[4];
    const float* layer_Wi  = (const float*)d_in[5];
    const float* out_w     = (const float*)d_in[6];
    float* out = (float*)d_out;

    const int smem_layers = (NB * DD + 2 * NB * NN + 2 * DD * 36) * sizeof(float);
    cudaFuncSetAttribute(k_layers2,   cudaFuncAttributeMaxDynamicSharedMemorySize, smem_layers);
    cudaFuncSetAttribute(k_logits_wg, cudaFuncAttributeMaxDynamicSharedMemorySize, (int)SMEM_PIPE);

    k_tables<<<(RES + 255) / 256, 256>>>();
    k_recur<<<BB, DD>>>(input_ids, emb, out);
    k_split_w<<<(WROWS * 32) / 256, 256>>>(out_w);   // independent of recur/layers
    k_layers2<<<SS * 2, 256, smem_layers>>>(layer_W, layer_b, layer_Wr, layer_Wi);

    k_logits_wg<<<CHUNKS, 512, SMEM_PIPE>>>(out);
}